// round 4
// baseline (speedup 1.0000x reference)
#include <cuda_runtime.h>

#define HW 512
#define PLANES 32            // B*C = 16*2
#define STRIPS 32
#define SROWS (HW / STRIPS)  // 16
#define TPB 64               // 8 columns per thread
#define GRADBX 8             // extra blockIdx.x values for grad work
#define NBLOCKS ((STRIPS + GRADBX) * PLANES)   // 1280 total blocks

#define GN (16 * 2 * 256 * 256)   // dvf elements
#define GPART (GRADBX * PLANES)   // 256 grad blocks

// scratch (no cudaMalloc allowed)
__device__ float g_ncc_part[PLANES * STRIPS];   // 1024
__device__ float g_dx_part[GPART];
__device__ float g_dy_part[GPART];
__device__ unsigned int g_counter = 0;

__device__ __forceinline__ float4 ld4(const float* __restrict__ p, int r, int x) {
    if ((unsigned)r < (unsigned)HW)
        return *reinterpret_cast<const float4*>(p + (size_t)r * HW + x);
    return make_float4(0.f, 0.f, 0.f, 0.f);
}

__device__ __forceinline__ void ld8(const float* __restrict__ p, int r, int x,
                                    float* __restrict__ d) {
    float4 v0 = ld4(p, r, x);
    float4 v1 = ld4(p, r, x + 4);
    d[0] = v0.x; d[1] = v0.y; d[2] = v0.z; d[3] = v0.w;
    d[4] = v1.x; d[5] = v1.y; d[6] = v1.z; d[7] = v1.w;
}

// horizontal 9-sum for 8 outputs: own 8 vertical sums in registers,
// L = left neighbor's upper 4 sums, R = right neighbor's lower 4 sums.
__device__ __forceinline__ void hsum8(const float4 L, const float4 R,
                                      const float* __restrict__ s,
                                      float* __restrict__ h) {
    float h0 = ((L.x + L.y) + (L.z + L.w)) + ((s[0] + s[1]) + (s[2] + s[3])) + s[4];
    h[0] = h0;
    h[1] = h[0] - L.x + s[5];
    h[2] = h[1] - L.y + s[6];
    h[3] = h[2] - L.z + s[7];
    h[4] = h[3] - L.w + R.x;
    h[5] = h[4] - s[0] + R.y;
    h[6] = h[5] - s[1] + R.z;
    h[7] = h[6] - s[2] + R.w;
}

__global__ __launch_bounds__(TPB) void fused_kernel(const float* __restrict__ gI,
                                                    const float* __restrict__ gJ,
                                                    const float* __restrict__ dvf,
                                                    float* __restrict__ out,
                                                    int out_size) {
    // exchange buffers: [buf][quantity][0=LO,1=HI][65] (LO[64]=0, HI[0]=0 halo)
    __shared__ __align__(16) float4 SH[2][5][2][TPB + 1];
    __shared__ double dred[TPB];
    __shared__ bool s_last;

    const int t = threadIdx.x;

    if (blockIdx.x < STRIPS) {
        // ───────────── NCC path ─────────────
        const int strip = blockIdx.x;
        const int plane = blockIdx.y;
        const float* I = gI + (size_t)plane * HW * HW;
        const float* J = gJ + (size_t)plane * HW * HW;
        const int x0 = t * 8;

        {   // zero whole exchange region (covers the halo cells)
            float4* z = &SH[0][0][0][0];
            const int tot = 2 * 5 * 2 * (TPB + 1);
            for (int i = t; i < tot; i += TPB) z[i] = make_float4(0.f, 0.f, 0.f, 0.f);
        }
        __syncthreads();

        float sI[8], sJ[8], sI2[8], sJ2[8], sIJ[8];
#pragma unroll
        for (int k = 0; k < 8; ++k) { sI[k]=0.f; sJ[k]=0.f; sI2[k]=0.f; sJ2[k]=0.f; sIJ[k]=0.f; }

        const int y0 = strip * SROWS;

        auto addrow = [&](int r) {
            float a[8], b[8];
            ld8(I, r, x0, a);
            ld8(J, r, x0, b);
#pragma unroll
            for (int k = 0; k < 8; ++k) {
                float iv = a[k], jv = b[k];
                sI[k]  += iv;
                sJ[k]  += jv;
                sI2[k] = fmaf(iv, iv, sI2[k]);
                sJ2[k] = fmaf(jv, jv, sJ2[k]);
                sIJ[k] = fmaf(iv, jv, sIJ[k]);
            }
        };
        auto subrow = [&](int r) {
            float a[8], b[8];
            ld8(I, r, x0, a);
            ld8(J, r, x0, b);
#pragma unroll
            for (int k = 0; k < 8; ++k) {
                float iv = a[k], jv = b[k];
                sI[k]  -= iv;
                sJ[k]  -= jv;
                sI2[k] = fmaf(-iv, iv, sI2[k]);
                sJ2[k] = fmaf(-jv, jv, sJ2[k]);
                sIJ[k] = fmaf(-iv, jv, sIJ[k]);
            }
        };

#pragma unroll
        for (int r = y0 - 4; r <= y0 + 3; ++r) addrow(r);

        const float inv81 = 1.f / 81.f;
        float acc = 0.f;

        for (int y = y0; y < y0 + SROWS; ++y) {
            addrow(y + 4);
            if (y > y0) subrow(y - 5);

            const int buf = y & 1;
            // publish: LO[t] = sums[0..3], HI[t+1] = sums[4..7]
            SH[buf][0][0][t]     = *reinterpret_cast<float4*>(&sI[0]);
            SH[buf][0][1][t + 1] = *reinterpret_cast<float4*>(&sI[4]);
            SH[buf][1][0][t]     = *reinterpret_cast<float4*>(&sJ[0]);
            SH[buf][1][1][t + 1] = *reinterpret_cast<float4*>(&sJ[4]);
            SH[buf][2][0][t]     = *reinterpret_cast<float4*>(&sI2[0]);
            SH[buf][2][1][t + 1] = *reinterpret_cast<float4*>(&sI2[4]);
            SH[buf][3][0][t]     = *reinterpret_cast<float4*>(&sJ2[0]);
            SH[buf][3][1][t + 1] = *reinterpret_cast<float4*>(&sJ2[4]);
            SH[buf][4][0][t]     = *reinterpret_cast<float4*>(&sIJ[0]);
            SH[buf][4][1][t + 1] = *reinterpret_cast<float4*>(&sIJ[4]);
            __syncthreads();   // single barrier per row (double buffering covers reuse)

            float hI[8], hJ[8], hI2[8], hJ2[8], hIJ[8];
            hsum8(SH[buf][0][1][t], SH[buf][0][0][t + 1], sI,  hI);
            hsum8(SH[buf][1][1][t], SH[buf][1][0][t + 1], sJ,  hJ);
            hsum8(SH[buf][2][1][t], SH[buf][2][0][t + 1], sI2, hI2);
            hsum8(SH[buf][3][1][t], SH[buf][3][0][t + 1], sJ2, hJ2);
            hsum8(SH[buf][4][1][t], SH[buf][4][0][t + 1], sIJ, hIJ);

#pragma unroll
            for (int k = 0; k < 8; ++k) {
                float tI = hI[k] * inv81;
                float tJ = hJ[k] * inv81;
                float cross = fmaf(-tI, hJ[k], hIJ[k]);
                float Ivar  = fmaf(-tI, hI[k], hI2[k]);
                float Jvar  = fmaf(-tJ, hJ[k], hJ2[k]);
                acc += __fdividef(cross * cross, fmaf(Ivar, Jvar, 1e-5f));
            }
        }

        __syncthreads();
        dred[t] = (double)acc;
        __syncthreads();
#pragma unroll
        for (int s = TPB / 2; s > 0; s >>= 1) {
            if (t < s) dred[t] += dred[t + s];
            __syncthreads();
        }
        if (t == 0) g_ncc_part[plane * STRIPS + strip] = (float)dred[0];
    } else {
        // ───────────── Grad path ─────────────
        const int gb = (blockIdx.x - STRIPS) * PLANES + blockIdx.y;   // 0..255
        const float* v = dvf;
        float ax = 0.f, ay = 0.f;
        for (int i = gb * TPB + t; i < GN; i += GPART * TPB) {
            float c = v[i];
            int x = i & 255;
            int y = (i >> 8) & 255;
            if (x < 255) { float d = v[i + 1] - c;   ax = fmaf(d, d, ax); }
            if (y < 255) { float d = v[i + 256] - c; ay = fmaf(d, d, ay); }
        }
        dred[t] = (double)ax;
        __syncthreads();
#pragma unroll
        for (int s = TPB / 2; s > 0; s >>= 1) {
            if (t < s) dred[t] += dred[t + s];
            __syncthreads();
        }
        if (t == 0) g_dx_part[gb] = (float)dred[0];
        __syncthreads();
        dred[t] = (double)ay;
        __syncthreads();
#pragma unroll
        for (int s = TPB / 2; s > 0; s >>= 1) {
            if (t < s) dred[t] += dred[t + s];
            __syncthreads();
        }
        if (t == 0) g_dy_part[gb] = (float)dred[0];
    }

    // ───────────── last-block finalize ─────────────
    if (t == 0) {
        __threadfence();
        unsigned int v = atomicAdd(&g_counter, 1u);
        s_last = (v == (unsigned)(NBLOCKS - 1));
    }
    __syncthreads();
    if (!s_last) return;
    __threadfence();

    // reduce NCC partials: 1024 entries, fixed order per thread
    {
        double a = 0.0;
#pragma unroll
        for (int i = 0; i < 16; ++i) a += (double)g_ncc_part[t * 16 + i];
        dred[t] = a;
    }
    __syncthreads();
#pragma unroll
    for (int s = TPB / 2; s > 0; s >>= 1) {
        if (t < s) dred[t] += dred[t + s];
        __syncthreads();
    }
    double Sncc = dred[0];
    __syncthreads();

    // reduce grad partials: 256 dx + 256 dy
    {
        double a = 0.0;
#pragma unroll
        for (int i = 0; i < 4; ++i)
            a += (double)g_dx_part[t * 4 + i] + (double)g_dy_part[t * 4 + i];
        dred[t] = a;
    }
    __syncthreads();
#pragma unroll
    for (int s = TPB / 2; s > 0; s >>= 1) {
        if (t < s) dred[t] += dred[t + s];
        __syncthreads();
    }
    double Sg = dred[0];

    if (t == 0) {
        double ncc  = -Sncc / 4194304.0;        // 16*512*512 ; (C-1) == 1
        double grad = 0.01 * (Sg / 2088960.0);  // 16*2*256*255
        double total = ncc + grad;
        if (out_size > 0) out[0] = (float)total;
        if (out_size > 1) out[1] = (float)ncc;
        if (out_size > 2) out[2] = (float)grad;
        g_counter = 0;   // reset for next graph replay
    }
}

extern "C" void kernel_launch(void* const* d_in, const int* in_sizes, int n_in,
                              void* d_out, int out_size) {
    const float* y_true = (const float*)d_in[0];
    const float* y_pred = (const float*)d_in[1];
    const float* dvf    = (const float*)d_in[2];

    dim3 grid(STRIPS + GRADBX, PLANES);
    fused_kernel<<<grid, TPB>>>(y_true, y_pred, dvf, (float*)d_out, out_size);
}

// round 7
// speedup vs baseline: 1.0466x; 1.0466x over previous
#include <cuda_runtime.h>

#define HW 512
#define PLANES 32            // B*C = 16*2
#define STRIPS 32
#define SROWS (HW / STRIPS)  // 16
#define TPB 128              // 4 columns per thread
#define VW (HW + 8)          // 520, 4-halo each side (zero padded)

#define GN (16 * 2 * 256 * 256)   // dvf elements
#define GBLOCKS 128
#define GTPB 256

// scratch (no cudaMalloc allowed)
__device__ float g_ncc_part[PLANES * STRIPS];   // 1024
__device__ float g_dx_part[GBLOCKS];
__device__ float g_dy_part[GBLOCKS];
__device__ unsigned int g_counter = 0;

__device__ __forceinline__ float4 ld4(const float* __restrict__ p, int r, int x) {
    if ((unsigned)r < (unsigned)HW)
        return *reinterpret_cast<const float4*>(p + (size_t)r * HW + x);
    return make_float4(0.f, 0.f, 0.f, 0.f);
}

// horizontal 9-sum: own 4 vertical sums stay in registers, only neighbors come
// from shared. L = V[x0..x0+3] (left neighbor), R = V[x0+8..x0+11] (right).
__device__ __forceinline__ void hsum9(const float4 L, const float4 R,
                                      const float* __restrict__ O,
                                      float* __restrict__ h) {
    float h0 = ((L.x + L.y) + (L.z + L.w)) + ((O[0] + O[1]) + (O[2] + O[3])) + R.x;
    h[0] = h0;
    h[1] = h0   - L.x + R.y;
    h[2] = h[1] - L.y + R.z;
    h[3] = h[2] - L.z + R.w;
}

__global__ __launch_bounds__(TPB, 8) void ncc_kernel(const float* __restrict__ gI,
                                                     const float* __restrict__ gJ) {
    const int strip = blockIdx.x;
    const int plane = blockIdx.y;
    const float* I = gI + (size_t)plane * HW * HW;
    const float* J = gJ + (size_t)plane * HW * HW;

    // double-buffered row-sum arrays: [buf][quantity][col]
    __shared__ __align__(16) float V[2][5][VW];
    __shared__ float red[TPB];

    const int t = threadIdx.x;
    const int x0 = t * 4;

    for (int i = t; i < VW; i += TPB) {
#pragma unroll
        for (int b = 0; b < 2; ++b)
#pragma unroll
            for (int q = 0; q < 5; ++q)
                V[b][q][i] = 0.f;
    }
    __syncthreads();

    // vertical running sums for this thread's 4 columns, held in registers
    __align__(16) float sI[4]  = {0.f, 0.f, 0.f, 0.f};
    __align__(16) float sJ[4]  = {0.f, 0.f, 0.f, 0.f};
    __align__(16) float sI2[4] = {0.f, 0.f, 0.f, 0.f};
    __align__(16) float sJ2[4] = {0.f, 0.f, 0.f, 0.f};
    __align__(16) float sIJ[4] = {0.f, 0.f, 0.f, 0.f};

    const int y0 = strip * SROWS;

    auto addrow = [&](int r) {
        float4 a = ld4(I, r, x0);
        float4 b = ld4(J, r, x0);
        const float* ap = reinterpret_cast<const float*>(&a);
        const float* bp = reinterpret_cast<const float*>(&b);
#pragma unroll
        for (int k = 0; k < 4; ++k) {
            float iv = ap[k], jv = bp[k];
            sI[k]  += iv;
            sJ[k]  += jv;
            sI2[k] = fmaf(iv, iv, sI2[k]);
            sJ2[k] = fmaf(jv, jv, sJ2[k]);
            sIJ[k] = fmaf(iv, jv, sIJ[k]);
        }
    };
    auto subrow = [&](int r) {
        float4 a = ld4(I, r, x0);
        float4 b = ld4(J, r, x0);
        const float* ap = reinterpret_cast<const float*>(&a);
        const float* bp = reinterpret_cast<const float*>(&b);
#pragma unroll
        for (int k = 0; k < 4; ++k) {
            float iv = ap[k], jv = bp[k];
            sI[k]  -= iv;
            sJ[k]  -= jv;
            sI2[k] = fmaf(-iv, iv, sI2[k]);
            sJ2[k] = fmaf(-jv, jv, sJ2[k]);
            sIJ[k] = fmaf(-iv, jv, sIJ[k]);
        }
    };

#pragma unroll
    for (int r = y0 - 4; r <= y0 + 3; ++r) addrow(r);

    const float inv81 = 1.f / 81.f;
    float acc = 0.f;

    for (int y = y0; y < y0 + SROWS; ++y) {
        addrow(y + 4);
        if (y > y0) subrow(y - 5);

        const int buf = y & 1;
        float (* __restrict__ Vb)[VW] = V[buf];

        // publish own vertical sums (halo cols [0..3],[516..519] stay zero)
        *reinterpret_cast<float4*>(&Vb[0][4 + x0]) = *reinterpret_cast<float4*>(sI);
        *reinterpret_cast<float4*>(&Vb[1][4 + x0]) = *reinterpret_cast<float4*>(sJ);
        *reinterpret_cast<float4*>(&Vb[2][4 + x0]) = *reinterpret_cast<float4*>(sI2);
        *reinterpret_cast<float4*>(&Vb[3][4 + x0]) = *reinterpret_cast<float4*>(sJ2);
        *reinterpret_cast<float4*>(&Vb[4][4 + x0]) = *reinterpret_cast<float4*>(sIJ);
        __syncthreads();   // single barrier per row (double buffering covers reuse)

        float hI[4], hJ[4], hI2[4], hJ2[4], hIJ[4];
        hsum9(*reinterpret_cast<const float4*>(&Vb[0][x0]),
              *reinterpret_cast<const float4*>(&Vb[0][x0 + 8]), sI,  hI);
        hsum9(*reinterpret_cast<const float4*>(&Vb[1][x0]),
              *reinterpret_cast<const float4*>(&Vb[1][x0 + 8]), sJ,  hJ);
        hsum9(*reinterpret_cast<const float4*>(&Vb[2][x0]),
              *reinterpret_cast<const float4*>(&Vb[2][x0 + 8]), sI2, hI2);
        hsum9(*reinterpret_cast<const float4*>(&Vb[3][x0]),
              *reinterpret_cast<const float4*>(&Vb[3][x0 + 8]), sJ2, hJ2);
        hsum9(*reinterpret_cast<const float4*>(&Vb[4][x0]),
              *reinterpret_cast<const float4*>(&Vb[4][x0 + 8]), sIJ, hIJ);

#pragma unroll
        for (int k = 0; k < 4; ++k) {
            float tI = hI[k] * inv81;
            float tJ = hJ[k] * inv81;
            float cross = fmaf(-tI, hJ[k], hIJ[k]);
            float Ivar  = fmaf(-tI, hI[k], hI2[k]);
            float Jvar  = fmaf(-tJ, hJ[k], hJ2[k]);
            acc += __fdividef(cross * cross, fmaf(Ivar, Jvar, 1e-5f));
        }
    }

    // block reduction (fixed topology -> deterministic)
    __syncthreads();
    red[t] = acc;
    __syncthreads();
#pragma unroll
    for (int s = TPB / 2; s > 0; s >>= 1) {
        if (t < s) red[t] += red[t + s];
        __syncthreads();
    }
    if (t == 0) g_ncc_part[plane * STRIPS + strip] = red[0];
}

// grad + finalize: stream order guarantees ncc_kernel is complete before this
// kernel starts, so the last grad block can safely do the global reduction.
__global__ __launch_bounds__(GTPB) void grad_finalize_kernel(const float* __restrict__ v,
                                                             float* __restrict__ out,
                                                             int out_size) {
    __shared__ double dred[GTPB];
    __shared__ bool s_last;
    const int t = threadIdx.x;

    float ax = 0.f, ay = 0.f;
    for (int i = blockIdx.x * GTPB + t; i < GN; i += GBLOCKS * GTPB) {
        float c = v[i];
        int x = i & 255;
        int y = (i >> 8) & 255;
        if (x < 255) { float d = v[i + 1] - c;   ax = fmaf(d, d, ax); }
        if (y < 255) { float d = v[i + 256] - c; ay = fmaf(d, d, ay); }
    }
    dred[t] = (double)ax;
    __syncthreads();
#pragma unroll
    for (int s = GTPB / 2; s > 0; s >>= 1) {
        if (t < s) dred[t] += dred[t + s];
        __syncthreads();
    }
    if (t == 0) g_dx_part[blockIdx.x] = (float)dred[0];
    __syncthreads();
    dred[t] = (double)ay;
    __syncthreads();
#pragma unroll
    for (int s = GTPB / 2; s > 0; s >>= 1) {
        if (t < s) dred[t] += dred[t + s];
        __syncthreads();
    }
    if (t == 0) g_dy_part[blockIdx.x] = (float)dred[0];

    // last-block finalize (counter over 128 homogeneous blocks)
    if (t == 0) {
        __threadfence();
        unsigned int c = atomicAdd(&g_counter, 1u);
        s_last = (c == (unsigned)(GBLOCKS - 1));
    }
    __syncthreads();
    if (!s_last) return;
    __threadfence();

    // reduce NCC partials: 1024 entries, fixed order
    {
        double a = 0.0;
#pragma unroll
        for (int i = 0; i < 4; ++i) a += (double)g_ncc_part[t * 4 + i];
        dred[t] = a;
    }
    __syncthreads();
#pragma unroll
    for (int s = GTPB / 2; s > 0; s >>= 1) {
        if (t < s) dred[t] += dred[t + s];
        __syncthreads();
    }
    double Sncc = dred[0];
    __syncthreads();

    // reduce grad partials: 128 dx + 128 dy
    dred[t] = (t < GBLOCKS) ? (double)g_dx_part[t] + (double)g_dy_part[t] : 0.0;
    __syncthreads();
#pragma unroll
    for (int s = GTPB / 2; s > 0; s >>= 1) {
        if (t < s) dred[t] += dred[t + s];
        __syncthreads();
    }
    double Sg = dred[0];

    if (t == 0) {
        double ncc  = -Sncc / 4194304.0;        // 16*512*512 ; (C-1) == 1
        double grad = 0.01 * (Sg / 2088960.0);  // 16*2*256*255
        double total = ncc + grad;
        if (out_size > 0) out[0] = (float)total;
        if (out_size > 1) out[1] = (float)ncc;
        if (out_size > 2) out[2] = (float)grad;
        g_counter = 0;   // reset for next graph replay
    }
}

extern "C" void kernel_launch(void* const* d_in, const int* in_sizes, int n_in,
                              void* d_out, int out_size) {
    const float* y_true = (const float*)d_in[0];
    const float* y_pred = (const float*)d_in[1];
    const float* dvf    = (const float*)d_in[2];

    dim3 grid(STRIPS, PLANES);
    ncc_kernel<<<grid, TPB>>>(y_true, y_pred);
    grad_finalize_kernel<<<GBLOCKS, GTPB>>>(dvf, (float*)d_out, out_size);
}